// round 1
// baseline (speedup 1.0000x reference)
#include <cuda_runtime.h>
#include <math.h>

// Problem constants (match reference)
#define B_  8
#define C_  3
#define H_  512
#define W_  512
#define FR_ 3
#define KS_ 7

#define TILE   32
#define HALO   (TILE + 2*FR_)   // 38
#define PITCH  40               // padded row to keep alignment
#define NTHREADS 256
#define NBLOCKS  (B_ * (H_/TILE) * (W_/TILE))   // 8*16*16 = 2048

// Scratch for block partial sums (no device allocation allowed)
__device__ float g_partials[NBLOCKS];

__device__ __forceinline__ int reflect_idx(int i, int n) {
    // jnp.pad 'reflect' (mirror, no edge repeat); FR < n so one fold suffices
    if (i < 0) i = -i;
    if (i >= n) i = 2*n - 2 - i;
    return i;
}

__global__ __launch_bounds__(NTHREADS, 4)
void blt_loss_kernel(const float* __restrict__ in)
{
    __shared__ float tile[C_][HALO][PITCH];

    const int tid = threadIdx.x;
    const int tx  = tid & 31;          // 0..31 (x within tile)
    const int ty  = tid >> 5;          // 0..7
    const int x0  = blockIdx.x * TILE;
    const int y0  = blockIdx.y * TILE;
    const int b   = blockIdx.z;

    // ---- load tile + halo with reflect padding ----
    const float* base = in + (size_t)b * C_ * H_ * W_;
    for (int idx = tid; idx < C_ * HALO * HALO; idx += NTHREADS) {
        int c   = idx / (HALO * HALO);
        int rem = idx - c * (HALO * HALO);
        int iy  = rem / HALO;
        int ix  = rem - iy * HALO;
        int gy  = reflect_idx(y0 - FR_ + iy, H_);
        int gx  = reflect_idx(x0 - FR_ + ix, W_);
        tile[c][iy][ix] = base[(c * H_ + gy) * W_ + gx];
    }
    __syncthreads();

    // 1D Gaussian (sigma=1), normalized 2D kernel = gk[k]*gk[l] / S^2
    // sum g = 1 + 2*(e^-0.5 + e^-2 + e^-4.5) = 2.5059498789749768
    // invS2 = 1 / sum^2
    const float invS2 = 0.15924113893827554f;
    const float g1 = 0.6065306597126334f;
    const float g2 = 0.1353352832366127f;
    const float g3 = 0.011108996538242306f;
    const float gk[KS_] = { g3, g2, g1, 1.0f, g1, g2, g3 };

    const float inv2sr2 = 50.0f;  // 1/(2*0.1^2)

    float acc = 0.0f;

    #pragma unroll
    for (int p = 0; p < 4; p++) {
        const int py = ty + 8 * p;      // 0..31
        const int px = tx;

        const float c0 = tile[0][py + FR_][px + FR_];
        const float c1 = tile[1][py + FR_][px + FR_];
        const float c2 = tile[2][py + FR_][px + FR_];

        #pragma unroll
        for (int k = 0; k < KS_; k++) {
            const float gkv = gk[k] * invS2;
            #pragma unroll
            for (int l = 0; l < KS_; l++) {
                const float n0 = tile[0][py + k][px + l];
                const float n1 = tile[1][py + k][px + l];
                const float n2 = tile[2][py + k][px + l];
                const float d0 = c0 - n0;
                const float d1 = c1 - n1;
                const float d2 = c2 - n2;
                const float s  = d0*d0 + d1*d1 + d2*d2;
                const float w  = __expf(-inv2sr2 * s) * (gkv * gk[l]);
                acc = fmaf(fabsf(d0) + fabsf(d1) + fabsf(d2), w, acc);
            }
        }
    }

    // ---- block reduction (warp shuffle + smem) ----
    #pragma unroll
    for (int ofs = 16; ofs > 0; ofs >>= 1)
        acc += __shfl_down_sync(0xffffffffu, acc, ofs);

    __shared__ float warp_sums[NTHREADS / 32];
    if (tx == 0) warp_sums[ty] = acc;
    __syncthreads();

    if (tid == 0) {
        float bs = 0.0f;
        #pragma unroll
        for (int wi = 0; wi < NTHREADS / 32; wi++) bs += warp_sums[wi];
        const int bidx = (blockIdx.z * gridDim.y + blockIdx.y) * gridDim.x + blockIdx.x;
        g_partials[bidx] = bs;
    }
}

__global__ void blt_final_reduce(float* __restrict__ out)
{
    __shared__ double sh[256];
    double s = 0.0;
    for (int i = threadIdx.x; i < NBLOCKS; i += 256)
        s += (double)g_partials[i];
    sh[threadIdx.x] = s;
    __syncthreads();
    for (int ofs = 128; ofs > 0; ofs >>= 1) {
        if (threadIdx.x < ofs) sh[threadIdx.x] += sh[threadIdx.x + ofs];
        __syncthreads();
    }
    if (threadIdx.x == 0)
        out[0] = (float)(sh[0] / (double)((size_t)B_ * C_ * H_ * W_));
}

extern "C" void kernel_launch(void* const* d_in, const int* in_sizes, int n_in,
                              void* d_out, int out_size)
{
    const float* in = (const float*)d_in[0];
    float* out = (float*)d_out;

    dim3 grid(W_ / TILE, H_ / TILE, B_);   // 16,16,8
    blt_loss_kernel<<<grid, NTHREADS>>>(in);
    blt_final_reduce<<<1, 256>>>(out);
}

// round 3
// speedup vs baseline: 1.0245x; 1.0245x over previous
#include <cuda_runtime.h>
#include <math.h>

// Problem constants
#define B_  8
#define C_  3
#define H_  512
#define W_  512
#define FR_ 3
#define KS_ 7

#define TILE   32
#define HALO   (TILE + 2*FR_)   // 38
#define PITCH  40
#define NT     256
#define NBLOCKS (B_ * (H_/TILE) * (W_/TILE))   // 2048

typedef unsigned long long u64;

// Scratch (no device allocation allowed)
__device__ float        g_partials[NBLOCKS];
__device__ unsigned int g_done = 0;   // self-resetting via atomicInc wrap

// ---- f32x2 packed helpers (sm_103a) ----
__device__ __forceinline__ u64 pk2(float a, float b) {
    u64 r; asm("mov.b64 %0, {%1,%2};" : "=l"(r) : "f"(a), "f"(b)); return r;
}
__device__ __forceinline__ void upk2(u64 v, float& a, float& b) {
    asm("mov.b64 {%0,%1}, %2;" : "=f"(a), "=f"(b) : "l"(v));
}
__device__ __forceinline__ u64 mul2(u64 a, u64 b) {
    u64 r; asm("mul.rn.f32x2 %0,%1,%2;" : "=l"(r) : "l"(a), "l"(b)); return r;
}
__device__ __forceinline__ u64 add2(u64 a, u64 b) {
    u64 r; asm("add.rn.f32x2 %0,%1,%2;" : "=l"(r) : "l"(a), "l"(b)); return r;
}
__device__ __forceinline__ u64 fma2(u64 a, u64 b, u64 c) {
    u64 r; asm("fma.rn.f32x2 %0,%1,%2,%3;" : "=l"(r) : "l"(a), "l"(b), "l"(c)); return r;
}
__device__ __forceinline__ u64 abs2(u64 a) { return a & 0x7FFFFFFF7FFFFFFFull; }
__device__ __forceinline__ float ex2f(float x) {
    float r; asm("ex2.approx.ftz.f32 %0,%1;" : "=f"(r) : "f"(x)); return r;
}

__device__ __forceinline__ int reflect_idx(int i, int n) {
    if (i < 0) i = -i;
    if (i >= n) i = 2*n - 2 - i;
    return i;
}

__global__ __launch_bounds__(NT, 2)
void blt_loss_kernel(const float* __restrict__ in, float* __restrict__ out)
{
    __shared__ float tile[C_][HALO][PITCH];
    __shared__ float warp_sums[NT / 32];
    __shared__ int   is_last;

    const int tid = threadIdx.x;
    const int x0b = blockIdx.x * TILE;
    const int y0b = blockIdx.y * TILE;
    const int b   = blockIdx.z;

    // ---- load tile + halo (reflect) ----
    const float* base = in + (size_t)b * C_ * H_ * W_;
    for (int idx = tid; idx < C_ * HALO * HALO; idx += NT) {
        int c   = idx / (HALO * HALO);
        int rem = idx - c * (HALO * HALO);
        int iy  = rem / HALO;
        int ix  = rem - iy * HALO;
        int gy  = reflect_idx(y0b - FR_ + iy, H_);
        int gx  = reflect_idx(x0b - FR_ + ix, W_);
        tile[c][iy][ix] = base[(c * H_ + gy) * W_ + gx];
    }
    __syncthreads();

    // Thread -> 4 consecutive x pixels in one row (2 packed pairs)
    const int ty = tid >> 3;          // 0..31
    const int x0 = (tid & 7) * 4;     // 0..28

    // Centers: pixel x -> tile col x+FR_. pairA = (x0, x0+1), pairB = (x0+2, x0+3)
    u64 cA[C_], cB[C_];
    #pragma unroll
    for (int c = 0; c < C_; c++) {
        cA[c] = pk2(tile[c][ty+FR_][x0+3], tile[c][ty+FR_][x0+4]);
        cB[c] = pk2(tile[c][ty+FR_][x0+5], tile[c][ty+FR_][x0+6]);
    }

    // ex2( -50*log2(e) * s + log2(A*gk*gl) )
    const float LOG2A = -2.65056562f;                   // log2(1/2.5059499^2)
    const float LGK[4] = { 0.0f, -0.72134751f, -2.88539004f, -6.49212760f };
    const u64 SC2  = pk2(-72.13475204f, -72.13475204f); // -50*log2(e)
    const u64 NEG1 = pk2(-1.0f, -1.0f);

    u64 accA = pk2(0.0f, 0.0f);
    u64 accB = pk2(0.0f, 0.0f);

    #pragma unroll
    for (int k = 0; k < KS_; k++) {
        // window: cols x0 .. x0+9 per channel, as aligned float2
        float2 f[C_][5];
        #pragma unroll
        for (int c = 0; c < C_; c++)
            #pragma unroll
            for (int j = 0; j < 5; j++)
                f[c][j] = *(const float2*)&tile[c][ty+k][x0 + 2*j];

        const float lgk = LGK[(k < FR_) ? (FR_ - k) : (k - FR_)];

        #pragma unroll
        for (int l = 0; l < KS_; l++) {
            if (k == FR_ && l == FR_) continue;  // center tap: d=0 -> 0

            const float lc = LOG2A + lgk + LGK[(l < FR_) ? (FR_ - l) : (l - FR_)];
            const u64 lc2 = pk2(lc, lc);

            u64 nA[C_], nB[C_];
            #pragma unroll
            for (int c = 0; c < C_; c++) {
                if ((l & 1) == 0) {
                    nA[c] = pk2(f[c][l/2].x,     f[c][l/2].y);
                    nB[c] = pk2(f[c][l/2+1].x,   f[c][l/2+1].y);
                } else {
                    nA[c] = pk2(f[c][l/2].y,     f[c][l/2+1].x);
                    nB[c] = pk2(f[c][l/2+1].y,   f[c][l/2+2].x);
                }
            }

            // pair A
            {
                u64 d0 = fma2(nA[0], NEG1, cA[0]);
                u64 d1 = fma2(nA[1], NEG1, cA[1]);
                u64 d2 = fma2(nA[2], NEG1, cA[2]);
                u64 s  = fma2(d2, d2, fma2(d1, d1, mul2(d0, d0)));
                u64 t  = fma2(s, SC2, lc2);
                float tl, th; upk2(t, tl, th);
                u64 e  = pk2(ex2f(tl), ex2f(th));
                u64 L  = add2(abs2(d0), add2(abs2(d1), abs2(d2)));
                accA   = fma2(L, e, accA);
            }
            // pair B
            {
                u64 d0 = fma2(nB[0], NEG1, cB[0]);
                u64 d1 = fma2(nB[1], NEG1, cB[1]);
                u64 d2 = fma2(nB[2], NEG1, cB[2]);
                u64 s  = fma2(d2, d2, fma2(d1, d1, mul2(d0, d0)));
                u64 t  = fma2(s, SC2, lc2);
                float tl, th; upk2(t, tl, th);
                u64 e  = pk2(ex2f(tl), ex2f(th));
                u64 L  = add2(abs2(d0), add2(abs2(d1), abs2(d2)));
                accB   = fma2(L, e, accB);
            }
        }
    }

    // ---- reduce: thread -> warp -> block ----
    u64 accP = add2(accA, accB);
    float a0, a1; upk2(accP, a0, a1);
    float acc = a0 + a1;

    #pragma unroll
    for (int ofs = 16; ofs > 0; ofs >>= 1)
        acc += __shfl_down_sync(0xffffffffu, acc, ofs);

    if ((tid & 31) == 0) warp_sums[tid >> 5] = acc;
    __syncthreads();

    if (tid == 0) {
        float bs = 0.0f;
        #pragma unroll
        for (int wi = 0; wi < NT / 32; wi++) bs += warp_sums[wi];
        const int bidx = (blockIdx.z * gridDim.y + blockIdx.y) * gridDim.x + blockIdx.x;
        g_partials[bidx] = bs;
        __threadfence();
        unsigned int old = atomicInc(&g_done, NBLOCKS - 1);  // wraps to 0: self-reset
        is_last = (old == NBLOCKS - 1);
    }
    __syncthreads();

    // ---- last block: final deterministic reduce ----
    if (is_last) {
        float s = 0.0f;
        for (int i = tid; i < NBLOCKS; i += NT)
            s += __ldcg(&g_partials[i]);

        #pragma unroll
        for (int ofs = 16; ofs > 0; ofs >>= 1)
            s += __shfl_down_sync(0xffffffffu, s, ofs);

        if ((tid & 31) == 0) warp_sums[tid >> 5] = s;
        __syncthreads();

        if (tid == 0) {
            float total = 0.0f;
            #pragma unroll
            for (int wi = 0; wi < NT / 32; wi++) total += warp_sums[wi];
            out[0] = total * (1.0f / (float)((size_t)B_ * C_ * H_ * W_));
        }
    }
}

extern "C" void kernel_launch(void* const* d_in, const int* in_sizes, int n_in,
                              void* d_out, int out_size)
{
    const float* in = (const float*)d_in[0];
    float* out = (float*)d_out;

    dim3 grid(W_ / TILE, H_ / TILE, B_);   // 16,16,8
    blt_loss_kernel<<<grid, NT>>>(in, out);
}

// round 4
// speedup vs baseline: 1.0443x; 1.0194x over previous
#include <cuda_runtime.h>
#include <math.h>

#define B_  8
#define C_  3
#define H_  512
#define W_  512
#define FR_ 3
#define KS_ 7

#define TILE   32
#define HALO   (TILE + 2*FR_)   // 38
#define P2     20               // pitch in float2 (u64) units = 40 floats
#define NT     256
#define NBLOCKS (B_ * (H_/TILE) * (W_/TILE))   // 2048

typedef unsigned long long u64;

__device__ float        g_partials[NBLOCKS];
__device__ unsigned int g_done = 0;   // self-resetting via atomicInc wrap

// ---- f32x2 packed helpers (sm_103a) ----
__device__ __forceinline__ u64 pk2(float a, float b) {
    u64 r; asm("mov.b64 %0, {%1,%2};" : "=l"(r) : "f"(a), "f"(b)); return r;
}
__device__ __forceinline__ void upk2(u64 v, float& a, float& b) {
    asm("mov.b64 {%0,%1}, %2;" : "=f"(a), "=f"(b) : "l"(v));
}
__device__ __forceinline__ u64 mul2(u64 a, u64 b) {
    u64 r; asm("mul.rn.f32x2 %0,%1,%2;" : "=l"(r) : "l"(a), "l"(b)); return r;
}
__device__ __forceinline__ u64 add2(u64 a, u64 b) {
    u64 r; asm("add.rn.f32x2 %0,%1,%2;" : "=l"(r) : "l"(a), "l"(b)); return r;
}
__device__ __forceinline__ u64 fma2(u64 a, u64 b, u64 c) {
    u64 r; asm("fma.rn.f32x2 %0,%1,%2,%3;" : "=l"(r) : "l"(a), "l"(b), "l"(c)); return r;
}
__device__ __forceinline__ u64 abs2(u64 a) { return a & 0x7FFFFFFF7FFFFFFFull; }
__device__ __forceinline__ u64 ex2_2(u64 x) {
    u64 r;
    asm("{.reg .b32 lo,hi;\n\t"
        "mov.b64 {lo,hi}, %1;\n\t"
        "ex2.approx.ftz.f32 lo, lo;\n\t"
        "ex2.approx.ftz.f32 hi, hi;\n\t"
        "mov.b64 %0, {lo,hi};}" : "=l"(r) : "l"(x));
    return r;
}

__device__ __forceinline__ int reflect_idx(int i, int n) {
    if (i < 0) i = -i;
    if (i >= n) i = 2*n - 2 - i;
    return i;
}

__global__ __launch_bounds__(NT, 2)
void blt_loss_kernel(const float* __restrict__ in, float* __restrict__ out)
{
    // Two copies of the tile: tB shifted left by one float.
    // Every float2-aligned u64 read of tA gives cols (2i, 2i+1);
    // of tB gives cols (2i+1, 2i+2). All tap pairs become aligned LDS.64.
    __shared__ u64 tA[C_][HALO][P2];
    __shared__ u64 tB[C_][HALO][P2];
    __shared__ float warp_sums[NT / 32];
    __shared__ int   is_last;

    const int tid = threadIdx.x;
    const int x0b = blockIdx.x * TILE;
    const int y0b = blockIdx.y * TILE;
    const int b   = blockIdx.z;

    // ---- load tile + halo (reflect), write both copies ----
    {
        float* fA = (float*)tA;
        float* fB = (float*)tB;
        const float* base = in + (size_t)b * C_ * H_ * W_;
        for (int idx = tid; idx < C_ * HALO * HALO; idx += NT) {
            int c   = idx / (HALO * HALO);
            int rem = idx - c * (HALO * HALO);
            int iy  = rem / HALO;
            int ix  = rem - iy * HALO;
            int gy  = reflect_idx(y0b - FR_ + iy, H_);
            int gx  = reflect_idx(x0b - FR_ + ix, W_);
            float v = base[(c * H_ + gy) * W_ + gx];
            int off = (c * HALO + iy) * (2 * P2);
            fA[off + ix] = v;
            if (ix > 0) fB[off + ix - 1] = v;
        }
    }
    __syncthreads();

    // Thread -> 4 consecutive x pixels in one row (2 packed pairs)
    const int ty = tid >> 3;            // 0..31
    const int h  = (tid & 7) * 2;       // u64 base index; pixel x0 = 2h

    // Centers: pair A = pixel cols (x0+3, x0+4) = tB[h+1]; pair B = tB[h+2]
    u64 cA[C_], cB[C_];
    #pragma unroll
    for (int c = 0; c < C_; c++) {
        cA[c] = tB[c][ty + FR_][h + 1];
        cB[c] = tB[c][ty + FR_][h + 2];
    }

    // w = ex2( -50*log2e * s + log2(invS2 * gk * gl) )
    const float LOG2A = -2.65056562f;
    const float LGK[4] = { 0.0f, -0.72134751f, -2.88539004f, -6.49212760f };
    const u64 SC2  = pk2(-72.13475204f, -72.13475204f);
    const u64 NEG1 = pk2(-1.0f, -1.0f);

    u64 accA0 = 0, accA1 = 0, accB0 = 0, accB1 = 0;

    #pragma unroll
    for (int k = 0; k < KS_; k++) {
        // Row windows: all aligned u64 loads, no repacking needed.
        u64 a[C_][5], bb[C_][4];
        #pragma unroll
        for (int c = 0; c < C_; c++) {
            #pragma unroll
            for (int j = 0; j < 5; j++) a[c][j]  = tA[c][ty + k][h + j];
            #pragma unroll
            for (int j = 0; j < 4; j++) bb[c][j] = tB[c][ty + k][h + j];
        }

        const float lgk = LGK[(k < FR_) ? (FR_ - k) : (k - FR_)];

        #pragma unroll
        for (int l = 0; l < KS_; l++) {
            if (k == FR_ && l == FR_) continue;   // center taps contribute 0

            const float lc = LOG2A + lgk + LGK[(l < FR_) ? (FR_ - l) : (l - FR_)];
            const u64 lc2 = pk2(lc, lc);

            // neighbors: l even -> tA[l/2], l odd -> tB[(l-1)/2]; pair B is +1
            u64 nA0, nA1, nA2, nB0, nB1, nB2;
            if ((l & 1) == 0) {
                nA0 = a[0][l/2];     nA1 = a[1][l/2];     nA2 = a[2][l/2];
                nB0 = a[0][l/2 + 1]; nB1 = a[1][l/2 + 1]; nB2 = a[2][l/2 + 1];
            } else {
                nA0 = bb[0][l/2];     nA1 = bb[1][l/2];     nA2 = bb[2][l/2];
                nB0 = bb[0][l/2 + 1]; nB1 = bb[1][l/2 + 1]; nB2 = bb[2][l/2 + 1];
            }

            // pair A
            {
                u64 d0 = fma2(nA0, NEG1, cA[0]);
                u64 d1 = fma2(nA1, NEG1, cA[1]);
                u64 d2 = fma2(nA2, NEG1, cA[2]);
                u64 s  = fma2(d2, d2, fma2(d1, d1, mul2(d0, d0)));
                u64 e  = ex2_2(fma2(s, SC2, lc2));
                u64 L  = add2(abs2(d0), add2(abs2(d1), abs2(d2)));
                if (l & 1) accA1 = fma2(L, e, accA1);
                else       accA0 = fma2(L, e, accA0);
            }
            // pair B
            {
                u64 d0 = fma2(nB0, NEG1, cB[0]);
                u64 d1 = fma2(nB1, NEG1, cB[1]);
                u64 d2 = fma2(nB2, NEG1, cB[2]);
                u64 s  = fma2(d2, d2, fma2(d1, d1, mul2(d0, d0)));
                u64 e  = ex2_2(fma2(s, SC2, lc2));
                u64 L  = add2(abs2(d0), add2(abs2(d1), abs2(d2)));
                if (l & 1) accB1 = fma2(L, e, accB1);
                else       accB0 = fma2(L, e, accB0);
            }
        }
    }

    // ---- reduce: thread -> warp -> block ----
    u64 accP = add2(add2(accA0, accA1), add2(accB0, accB1));
    float a0, a1; upk2(accP, a0, a1);
    float acc = a0 + a1;

    #pragma unroll
    for (int ofs = 16; ofs > 0; ofs >>= 1)
        acc += __shfl_down_sync(0xffffffffu, acc, ofs);

    if ((tid & 31) == 0) warp_sums[tid >> 5] = acc;
    __syncthreads();

    if (tid == 0) {
        float bs = 0.0f;
        #pragma unroll
        for (int wi = 0; wi < NT / 32; wi++) bs += warp_sums[wi];
        const int bidx = (blockIdx.z * gridDim.y + blockIdx.y) * gridDim.x + blockIdx.x;
        g_partials[bidx] = bs;
        __threadfence();
        unsigned int old = atomicInc(&g_done, NBLOCKS - 1);  // wraps to 0: self-reset
        is_last = (old == NBLOCKS - 1);
    }
    __syncthreads();

    // ---- last block: final deterministic reduce ----
    if (is_last) {
        float s = 0.0f;
        for (int i = tid; i < NBLOCKS; i += NT)
            s += __ldcg(&g_partials[i]);

        #pragma unroll
        for (int ofs = 16; ofs > 0; ofs >>= 1)
            s += __shfl_down_sync(0xffffffffu, s, ofs);

        if ((tid & 31) == 0) warp_sums[tid >> 5] = s;
        __syncthreads();

        if (tid == 0) {
            float total = 0.0f;
            #pragma unroll
            for (int wi = 0; wi < NT / 32; wi++) total += warp_sums[wi];
            out[0] = total * (1.0f / (float)((size_t)B_ * C_ * H_ * W_));
        }
    }
}

extern "C" void kernel_launch(void* const* d_in, const int* in_sizes, int n_in,
                              void* d_out, int out_size)
{
    const float* in = (const float*)d_in[0];
    float* out = (float*)d_out;

    dim3 grid(W_ / TILE, H_ / TILE, B_);   // 16,16,8
    blt_loss_kernel<<<grid, NT>>>(in, out);
}

// round 5
// speedup vs baseline: 1.1479x; 1.0992x over previous
#include <cuda_runtime.h>
#include <math.h>

#define B_  8
#define C_  3
#define H_  512
#define W_  512
#define FR_ 3
#define KS_ 7

#define TILE   32
#define HALO   (TILE + 2*FR_)   // 38
#define P2     21               // pitch in u64 units (42 floats) -> conflict-free rows
#define NT     256
#define NBLOCKS (B_ * (H_/TILE) * (W_/TILE))   // 2048

typedef unsigned long long u64;

__device__ float        g_partials[NBLOCKS];
__device__ unsigned int g_done = 0;   // self-resetting via atomicInc wrap

// ---- f32x2 packed helpers (sm_103a) ----
__device__ __forceinline__ u64 pk2(float a, float b) {
    u64 r; asm("mov.b64 %0, {%1,%2};" : "=l"(r) : "f"(a), "f"(b)); return r;
}
__device__ __forceinline__ void upk2(u64 v, float& a, float& b) {
    asm("mov.b64 {%0,%1}, %2;" : "=f"(a), "=f"(b) : "l"(v));
}
__device__ __forceinline__ u64 mul2(u64 a, u64 b) {
    u64 r; asm("mul.rn.f32x2 %0,%1,%2;" : "=l"(r) : "l"(a), "l"(b)); return r;
}
__device__ __forceinline__ u64 add2(u64 a, u64 b) {
    u64 r; asm("add.rn.f32x2 %0,%1,%2;" : "=l"(r) : "l"(a), "l"(b)); return r;
}
__device__ __forceinline__ u64 fma2(u64 a, u64 b, u64 c) {
    u64 r; asm("fma.rn.f32x2 %0,%1,%2,%3;" : "=l"(r) : "l"(a), "l"(b), "l"(c)); return r;
}
__device__ __forceinline__ u64 abs2(u64 a) { return a & 0x7FFFFFFF7FFFFFFFull; }
__device__ __forceinline__ u64 ex2_2(u64 x) {
    u64 r;
    asm("{.reg .b32 lo,hi;\n\t"
        "mov.b64 {lo,hi}, %1;\n\t"
        "ex2.approx.ftz.f32 lo, lo;\n\t"
        "ex2.approx.ftz.f32 hi, hi;\n\t"
        "mov.b64 %0, {lo,hi};}" : "=l"(r) : "l"(x));
    return r;
}

__device__ __forceinline__ int reflect_idx(int i, int n) {
    if (i < 0) i = -i;
    if (i >= n) i = 2*n - 2 - i;
    return i;
}

__global__ __launch_bounds__(NT, 4)
void blt_loss_kernel(const float* __restrict__ in, float* __restrict__ out)
{
    // tA: tile; tB: tile shifted left by one float. All tap pairs -> aligned LDS.64.
    __shared__ u64 tA[C_][HALO][P2];
    __shared__ u64 tB[C_][HALO][P2];
    __shared__ float warp_sums[NT / 32];
    __shared__ int   is_last;

    const int tid = threadIdx.x;
    const int x0b = blockIdx.x * TILE;
    const int y0b = blockIdx.y * TILE;
    const int b   = blockIdx.z;

    // ---- load tile + halo (reflect), write both copies ----
    {
        float* fA = (float*)tA;
        float* fB = (float*)tB;
        const float* base = in + (size_t)b * C_ * H_ * W_;
        for (int idx = tid; idx < C_ * HALO * HALO; idx += NT) {
            int c   = idx / (HALO * HALO);
            int rem = idx - c * (HALO * HALO);
            int iy  = rem / HALO;
            int ix  = rem - iy * HALO;
            int gy  = reflect_idx(y0b - FR_ + iy, H_);
            int gx  = reflect_idx(x0b - FR_ + ix, W_);
            float v = base[(c * H_ + gy) * W_ + gx];
            int off = (c * HALO + iy) * (2 * P2);
            fA[off + ix] = v;
            if (ix > 0) fB[off + ix - 1] = v;
        }
    }
    __syncthreads();

    // Thread -> 4 consecutive x pixels in one row (2 packed pairs)
    const int ty = tid >> 3;            // 0..31
    const int h  = (tid & 7) * 2;       // u64 base index; pixel x0 = 2h

    u64 cA[C_], cB[C_];
    #pragma unroll
    for (int c = 0; c < C_; c++) {
        cA[c] = tB[c][ty + FR_][h + 1];
        cB[c] = tB[c][ty + FR_][h + 2];
    }

    const float LOG2A = -2.65056562f;
    const float LGK[4] = { 0.0f, -0.72134751f, -2.88539004f, -6.49212760f };
    const u64 SC2  = pk2(-72.13475204f, -72.13475204f);
    const u64 NEG1 = pk2(-1.0f, -1.0f);

    u64 accA0 = 0, accA1 = 0, accB0 = 0, accB1 = 0;

    #pragma unroll
    for (int k = 0; k < KS_; k++) {
        const float lgk = LGK[(k < FR_) ? (FR_ - k) : (k - FR_)];
        const int   row = ty + k;

        // Sliding 2-word windows per channel (low live-register count).
        u64 aP[C_], aC[C_], bP[C_], bC[C_];
        #pragma unroll
        for (int c = 0; c < C_; c++) {
            aP[c] = tA[c][row][h];
            aC[c] = tA[c][row][h + 1];
            bP[c] = tB[c][row][h];
            bC[c] = tB[c][row][h + 1];
        }

        #pragma unroll
        for (int l = 0; l < KS_; l++) {
            const bool odd = (l & 1);

            // slide: on each new even l>0, advance the A window; odd l>1 -> B window
            if (l >= 2) {
                if (!odd) {
                    #pragma unroll
                    for (int c = 0; c < C_; c++) {
                        aP[c] = aC[c];
                        aC[c] = tA[c][row][h + 1 + l/2];
                    }
                } else {
                    #pragma unroll
                    for (int c = 0; c < C_; c++) {
                        bP[c] = bC[c];
                        bC[c] = tB[c][row][h + 1 + l/2];
                    }
                }
            }
            if (k == FR_ && l == FR_) continue;   // center tap contributes 0

            const float lc = LOG2A + lgk + LGK[(l < FR_) ? (FR_ - l) : (l - FR_)];
            const u64 lc2 = pk2(lc, lc);

            const u64* nP = odd ? bP : aP;   // pair A neighbors
            const u64* nC = odd ? bC : aC;   // pair B neighbors

            // pair A
            {
                u64 d0 = fma2(nP[0], NEG1, cA[0]);
                u64 d1 = fma2(nP[1], NEG1, cA[1]);
                u64 d2 = fma2(nP[2], NEG1, cA[2]);
                u64 s  = fma2(d2, d2, fma2(d1, d1, mul2(d0, d0)));
                u64 e  = ex2_2(fma2(s, SC2, lc2));
                u64 L  = add2(abs2(d0), add2(abs2(d1), abs2(d2)));
                if (odd) accA1 = fma2(L, e, accA1);
                else     accA0 = fma2(L, e, accA0);
            }
            // pair B
            {
                u64 d0 = fma2(nC[0], NEG1, cB[0]);
                u64 d1 = fma2(nC[1], NEG1, cB[1]);
                u64 d2 = fma2(nC[2], NEG1, cB[2]);
                u64 s  = fma2(d2, d2, fma2(d1, d1, mul2(d0, d0)));
                u64 e  = ex2_2(fma2(s, SC2, lc2));
                u64 L  = add2(abs2(d0), add2(abs2(d1), abs2(d2)));
                if (odd) accB1 = fma2(L, e, accB1);
                else     accB0 = fma2(L, e, accB0);
            }
        }
    }

    // ---- reduce: thread -> warp -> block ----
    u64 accP = add2(add2(accA0, accA1), add2(accB0, accB1));
    float a0, a1; upk2(accP, a0, a1);
    float acc = a0 + a1;

    #pragma unroll
    for (int ofs = 16; ofs > 0; ofs >>= 1)
        acc += __shfl_down_sync(0xffffffffu, acc, ofs);

    if ((tid & 31) == 0) warp_sums[tid >> 5] = acc;
    __syncthreads();

    if (tid == 0) {
        float bs = 0.0f;
        #pragma unroll
        for (int wi = 0; wi < NT / 32; wi++) bs += warp_sums[wi];
        const int bidx = (blockIdx.z * gridDim.y + blockIdx.y) * gridDim.x + blockIdx.x;
        g_partials[bidx] = bs;
        __threadfence();
        unsigned int old = atomicInc(&g_done, NBLOCKS - 1);  // wraps to 0: self-reset
        is_last = (old == NBLOCKS - 1);
    }
    __syncthreads();

    // ---- last block: final deterministic reduce ----
    if (is_last) {
        float s = 0.0f;
        for (int i = tid; i < NBLOCKS; i += NT)
            s += __ldcg(&g_partials[i]);

        #pragma unroll
        for (int ofs = 16; ofs > 0; ofs >>= 1)
            s += __shfl_down_sync(0xffffffffu, s, ofs);

        if ((tid & 31) == 0) warp_sums[tid >> 5] = s;
        __syncthreads();

        if (tid == 0) {
            float total = 0.0f;
            #pragma unroll
            for (int wi = 0; wi < NT / 32; wi++) total += warp_sums[wi];
            out[0] = total * (1.0f / (float)((size_t)B_ * C_ * H_ * W_));
        }
    }
}

extern "C" void kernel_launch(void* const* d_in, const int* in_sizes, int n_in,
                              void* d_out, int out_size)
{
    const float* in = (const float*)d_in[0];
    float* out = (float*)d_out;

    dim3 grid(W_ / TILE, H_ / TILE, B_);   // 16,16,8
    blt_loss_kernel<<<grid, NT>>>(in, out);
}

// round 6
// speedup vs baseline: 1.2361x; 1.0768x over previous
#include <cuda_runtime.h>
#include <math.h>

#define B_  8
#define C_  3
#define H_  512
#define W_  512
#define FR_ 3
#define KS_ 7

#define TILE   32
#define HALO   (TILE + 2*FR_)   // 38
#define P2     21               // pitch in u64 units (42 floats): conflict-free rows
#define NT     256
#define NBLOCKS (B_ * (H_/TILE) * (W_/TILE))   // 2048

typedef unsigned long long u64;

__device__ float        g_partials[NBLOCKS];
__device__ unsigned int g_done = 0;   // self-resetting via atomicInc wrap

// ---- f32x2 packed helpers (sm_103a) ----
__device__ __forceinline__ void upk2(u64 v, float& a, float& b) {
    asm("mov.b64 {%0,%1}, %2;" : "=f"(a), "=f"(b) : "l"(v));
}
__device__ __forceinline__ u64 mul2(u64 a, u64 b) {
    u64 r; asm("mul.rn.f32x2 %0,%1,%2;" : "=l"(r) : "l"(a), "l"(b)); return r;
}
__device__ __forceinline__ u64 add2(u64 a, u64 b) {
    u64 r; asm("add.rn.f32x2 %0,%1,%2;" : "=l"(r) : "l"(a), "l"(b)); return r;
}
__device__ __forceinline__ u64 fma2(u64 a, u64 b, u64 c) {
    u64 r; asm("fma.rn.f32x2 %0,%1,%2,%3;" : "=l"(r) : "l"(a), "l"(b), "l"(c)); return r;
}
__device__ __forceinline__ u64 abs2(u64 a) { return a & 0x7FFFFFFF7FFFFFFFull; }
__device__ __forceinline__ u64 ex2_2(u64 x) {
    u64 r;
    asm("{.reg .b32 lo,hi;\n\t"
        "mov.b64 {lo,hi}, %1;\n\t"
        "ex2.approx.ftz.f32 lo, lo;\n\t"
        "ex2.approx.ftz.f32 hi, hi;\n\t"
        "mov.b64 %0, {lo,hi};}" : "=l"(r) : "l"(x));
    return r;
}
// broadcast a (compile-time) float into a packed u64 — folds to an immediate
__device__ __forceinline__ u64 bc2(float x) {
    unsigned int u = __float_as_uint(x);
    return ((u64)u << 32) | (u64)u;
}

__device__ __forceinline__ int reflect_idx(int i, int n) {
    if (i < 0) i = -i;
    if (i >= n) i = 2*n - 2 - i;
    return i;
}

__global__ __launch_bounds__(NT, 4)
void blt_loss_kernel(const float* __restrict__ in, float* __restrict__ out)
{
    // tA: tile; tB: tile shifted left by one float. All tap pairs -> aligned LDS.64.
    __shared__ u64 tA[C_][HALO][P2];
    __shared__ u64 tB[C_][HALO][P2];
    __shared__ float warp_sums[NT / 32];
    __shared__ int   is_last;

    const int tid = threadIdx.x;
    const int x0b = blockIdx.x * TILE;
    const int y0b = blockIdx.y * TILE;
    const int b   = blockIdx.z;

    // ---- load tile + halo (reflect), write both copies ----
    {
        float* fA = (float*)tA;
        float* fB = (float*)tB;
        const float* base = in + (size_t)b * C_ * H_ * W_;
        for (int idx = tid; idx < C_ * HALO * HALO; idx += NT) {
            int c   = idx / (HALO * HALO);
            int rem = idx - c * (HALO * HALO);
            int iy  = rem / HALO;
            int ix  = rem - iy * HALO;
            int gy  = reflect_idx(y0b - FR_ + iy, H_);
            int gx  = reflect_idx(x0b - FR_ + ix, W_);
            float v = base[(c * H_ + gy) * W_ + gx];
            int off = (c * HALO + iy) * (2 * P2);
            fA[off + ix] = v;
            if (ix > 0) fB[off + ix - 1] = v;
        }
    }
    __syncthreads();

    // Thread -> 4 consecutive x pixels in one row (2 packed pairs)
    const int ty = tid >> 3;            // 0..31
    const int h  = (tid & 7) * 2;       // u64 base index; pixel x0 = 2h

    u64 cA0 = tB[0][ty + FR_][h + 1];
    u64 cA1 = tB[1][ty + FR_][h + 1];
    u64 cA2 = tB[2][ty + FR_][h + 1];
    u64 cB0 = tB[0][ty + FR_][h + 2];
    u64 cB1 = tB[1][ty + FR_][h + 2];
    u64 cB2 = tB[2][ty + FR_][h + 2];

    const float LOG2A = -2.65056562f;
    const float LGK[4] = { 0.0f, -0.72134751f, -2.88539004f, -6.49212760f };
    const u64 SC2  = bc2(-72.13475204f);   // -50*log2(e)
    const u64 NEG1 = bc2(-1.0f);

    u64 accA0 = 0, accA1 = 0, accB0 = 0, accB1 = 0;

    #pragma unroll
    for (int k = 0; k < KS_; k++) {
        const int   row = ty + k;
        const float lgk = LGK[(k < FR_) ? (FR_ - k) : (k - FR_)];

        #pragma unroll
        for (int l = 0; l < KS_; l++) {
            if (k == FR_ && l == FR_) continue;   // center tap contributes 0

            const float lc  = LOG2A + lgk + LGK[(l < FR_) ? (FR_ - l) : (l - FR_)];
            const u64   lc2 = bc2(lc);
            const int   j   = l >> 1;

            // parity/index resolve at compile time under full unroll; identical
            // smem loads are CSE'd by the compiler (no manual windowing).
            u64 nA0 = (l & 1) ? tB[0][row][h + j] : tA[0][row][h + j];
            u64 nA1 = (l & 1) ? tB[1][row][h + j] : tA[1][row][h + j];
            u64 nA2 = (l & 1) ? tB[2][row][h + j] : tA[2][row][h + j];
            u64 nB0 = (l & 1) ? tB[0][row][h + j + 1] : tA[0][row][h + j + 1];
            u64 nB1 = (l & 1) ? tB[1][row][h + j + 1] : tA[1][row][h + j + 1];
            u64 nB2 = (l & 1) ? tB[2][row][h + j + 1] : tA[2][row][h + j + 1];

            // pair A
            {
                u64 d0 = fma2(nA0, NEG1, cA0);
                u64 d1 = fma2(nA1, NEG1, cA1);
                u64 d2 = fma2(nA2, NEG1, cA2);
                u64 s  = fma2(d2, d2, fma2(d1, d1, mul2(d0, d0)));
                u64 e  = ex2_2(fma2(s, SC2, lc2));
                u64 L  = add2(abs2(d0), add2(abs2(d1), abs2(d2)));
                if (l & 1) accA1 = fma2(L, e, accA1);
                else       accA0 = fma2(L, e, accA0);
            }
            // pair B
            {
                u64 d0 = fma2(nB0, NEG1, cB0);
                u64 d1 = fma2(nB1, NEG1, cB1);
                u64 d2 = fma2(nB2, NEG1, cB2);
                u64 s  = fma2(d2, d2, fma2(d1, d1, mul2(d0, d0)));
                u64 e  = ex2_2(fma2(s, SC2, lc2));
                u64 L  = add2(abs2(d0), add2(abs2(d1), abs2(d2)));
                if (l & 1) accB1 = fma2(L, e, accB1);
                else       accB0 = fma2(L, e, accB0);
            }
        }
    }

    // ---- reduce: thread -> warp -> block ----
    u64 accP = add2(add2(accA0, accA1), add2(accB0, accB1));
    float a0, a1; upk2(accP, a0, a1);
    float acc = a0 + a1;

    #pragma unroll
    for (int ofs = 16; ofs > 0; ofs >>= 1)
        acc += __shfl_down_sync(0xffffffffu, acc, ofs);

    if ((tid & 31) == 0) warp_sums[tid >> 5] = acc;
    __syncthreads();

    if (tid == 0) {
        float bs = 0.0f;
        #pragma unroll
        for (int wi = 0; wi < NT / 32; wi++) bs += warp_sums[wi];
        const int bidx = (blockIdx.z * gridDim.y + blockIdx.y) * gridDim.x + blockIdx.x;
        g_partials[bidx] = bs;
        __threadfence();
        unsigned int old = atomicInc(&g_done, NBLOCKS - 1);  // wraps to 0: self-reset
        is_last = (old == NBLOCKS - 1);
    }
    __syncthreads();

    // ---- last block: final deterministic reduce ----
    if (is_last) {
        float s = 0.0f;
        for (int i = tid; i < NBLOCKS; i += NT)
            s += __ldcg(&g_partials[i]);

        #pragma unroll
        for (int ofs = 16; ofs > 0; ofs >>= 1)
            s += __shfl_down_sync(0xffffffffu, s, ofs);

        if ((tid & 31) == 0) warp_sums[tid >> 5] = s;
        __syncthreads();

        if (tid == 0) {
            float total = 0.0f;
            #pragma unroll
            for (int wi = 0; wi < NT / 32; wi++) total += warp_sums[wi];
            out[0] = total * (1.0f / (float)((size_t)B_ * C_ * H_ * W_));
        }
    }
}

extern "C" void kernel_launch(void* const* d_in, const int* in_sizes, int n_in,
                              void* d_out, int out_size)
{
    const float* in = (const float*)d_in[0];
    float* out = (float*)d_out;

    dim3 grid(W_ / TILE, H_ / TILE, B_);   // 16,16,8
    blt_loss_kernel<<<grid, NT>>>(in, out);
}